// round 8
// baseline (speedup 1.0000x reference)
#include <cuda_runtime.h>
#include <cuda_fp16.h>
#include <cstdint>

#define NNODES_MAX 100000
#define EDGES_MAX  1600000
#define DH 128
#define NGRAPH 512

// ---------------- scratch (static device globals; no allocation) ------------
__device__ __half g_x16[NNODES_MAX * DH];    // input features, fp16
__device__ __half g_h16[NNODES_MAX * DH];    // layer output h, fp16
__device__ __half g_agg16[NNODES_MAX * DH];  // h + A*h, fp16
__device__ __half g_w16[3 * DH * DH];        // W0,W1,W2 in fp16
__device__ float  g_pool[NGRAPH * DH];       // per-graph sums (fp32)
__device__ float  g_cnt[NGRAPH];             // per-graph node counts
__device__ int    g_deg[NNODES_MAX];
__device__ int    g_cur[NNODES_MAX];
__device__ int    g_rowptr[NNODES_MAX + 1];
__device__ int    g_col[EDGES_MAX];

// ---------------- helpers ---------------------------------------------------
__device__ __forceinline__ void red2(float* p, float a, float b) {
    asm volatile("red.global.add.v2.f32 [%0], {%1,%2};"
                 :: "l"(p), "f"(a), "f"(b) : "memory");
}
__device__ __forceinline__ void acc8(float* a, uint4 v) {
    float2 f0 = __half22float2(*reinterpret_cast<__half2*>(&v.x));
    float2 f1 = __half22float2(*reinterpret_cast<__half2*>(&v.y));
    float2 f2 = __half22float2(*reinterpret_cast<__half2*>(&v.z));
    float2 f3 = __half22float2(*reinterpret_cast<__half2*>(&v.w));
    a[0] += f0.x; a[1] += f0.y; a[2] += f1.x; a[3] += f1.y;
    a[4] += f2.x; a[5] += f2.y; a[6] += f3.x; a[7] += f3.y;
}

// ---------------- init: zero pool/cnt/deg ------------------------------------
__global__ void init_kernel(int n) {
    int i = blockIdx.x * blockDim.x + threadIdx.x;
    if (i < NGRAPH * DH) g_pool[i] = 0.f;
    if (i < NGRAPH) g_cnt[i] = 0.f;
    if (i < n) g_deg[i] = 0;
}

// fused: degree histogram (over E) + per-graph node counts (over N)
__global__ void hist_count_kernel(const int* __restrict__ ei,
                                  const int* __restrict__ batch, int E, int N) {
    int i = blockIdx.x * blockDim.x + threadIdx.x;
    if (i < E) atomicAdd(&g_deg[ei[E + i]], 1);   // dst
    if (i < N) atomicAdd(&g_cnt[batch[i]], 1.0f);
}

// single-block exclusive scan of g_deg into g_rowptr; also seeds g_cur
__global__ void scan_kernel(int n) {
    const int T = 1024;
    __shared__ int part[T];
    int t = threadIdx.x;
    int C = (n + T - 1) / T;
    int beg = t * C;
    int end = beg + C < n ? beg + C : n;
    int s = 0;
    for (int i = beg; i < end; i++) s += g_deg[i];
    part[t] = s;
    __syncthreads();
    for (int off = 1; off < T; off <<= 1) {
        int v = (t >= off) ? part[t - off] : 0;
        __syncthreads();
        part[t] += v;
        __syncthreads();
    }
    int run = (t == 0) ? 0 : part[t - 1];
    for (int i = beg; i < end; i++) {
        g_rowptr[i] = run;
        g_cur[i]    = run;
        run += g_deg[i];
    }
    if (t == 0) g_rowptr[n] = part[T - 1];
}

__global__ void fill_kernel(const int* __restrict__ ei, int E) {
    int i = blockIdx.x * blockDim.x + threadIdx.x;
    if (i >= E) return;
    int s = ei[i];
    int d = ei[E + i];
    int pos = atomicAdd(&g_cur[d], 1);
    g_col[pos] = s;
}

// ---------------- converters -------------------------------------------------
__global__ void convert_x_kernel(const float4* __restrict__ x, int n4) {
    int i = blockIdx.x * blockDim.x + threadIdx.x;
    if (i >= n4) return;
    float4 v = x[i];
    __half2* dst = reinterpret_cast<__half2*>(g_x16);
    dst[i * 2]     = __floats2half2_rn(v.x, v.y);
    dst[i * 2 + 1] = __floats2half2_rn(v.z, v.w);
}

__global__ void convert_w_kernel(const float4* __restrict__ w, int layer) {
    int i = blockIdx.x * blockDim.x + threadIdx.x;
    const int n4 = DH * DH / 4;   // 4096
    if (i >= n4) return;
    float4 v = w[i];
    __half2* dst = reinterpret_cast<__half2*>(&g_w16[layer * DH * DH]);
    dst[i * 2]     = __floats2half2_rn(v.x, v.y);
    dst[i * 2 + 1] = __floats2half2_rn(v.z, v.w);
}

// ---------------- gather: agg16[n] = src[n] + sum_{j in N(n)} src[j] ---------
// 16 lanes per node (lane handles 8 halfs = uint4 = 16B); 2 nodes per warp.
// Serial shfl loop (width 16). No early exit: node clamped, duplicate store benign.
__global__ void gather16_kernel(const __half* __restrict__ srcp, int N) {
    int t    = blockIdx.x * blockDim.x + threadIdx.x;
    int node = t >> 4;
    int sub  = threadIdx.x & 15;
    if (node >= N) node = N - 1;      // keep all warp lanes active for shfl
    const uint4* __restrict__ src = reinterpret_cast<const uint4*>(srcp);

    const int beg = g_rowptr[node];
    const int end = g_rowptr[node + 1];

    float a[8] = {0.f, 0.f, 0.f, 0.f, 0.f, 0.f, 0.f, 0.f};
    acc8(a, src[node * 16 + sub]);    // seed: own features

    for (int base = beg; base < end; base += 16) {
        int idx = (base + sub < end) ? g_col[base + sub] : 0;
        int cnt = end - base; if (cnt > 16) cnt = 16;
#pragma unroll 4
        for (int j = 0; j < cnt; j++) {
            int s = __shfl_sync(0xffffffffu, idx, j, 16);
            acc8(a, src[s * 16 + sub]);
        }
    }
    uint4 o;
    *reinterpret_cast<__half2*>(&o.x) = __floats2half2_rn(a[0], a[1]);
    *reinterpret_cast<__half2*>(&o.y) = __floats2half2_rn(a[2], a[3]);
    *reinterpret_cast<__half2*>(&o.z) = __floats2half2_rn(a[4], a[5]);
    *reinterpret_cast<__half2*>(&o.w) = __floats2half2_rn(a[6], a[7]);
    reinterpret_cast<uint4*>(g_agg16)[node * 16 + sub] = o;
}

// ---------------- tensor-core GEMM: C = act( agg16 @ W^T + b ) ---------------
// mma.sync m16n8k16 f16*f16+f32. BM=128, BN=128, BK=64 (2 stages), 8 warps.
// warp (wid%2, wid/2) owns m64 x n32 = 4x4 mma tiles. ldmatrix fragment loads.
template<bool RELU, bool POOL>
__global__ __launch_bounds__(256)
void hgemm_kernel(const __half* __restrict__ Wh, const float* __restrict__ bias,
                  const int* __restrict__ batch, int M) {
    __shared__ __half As[128 * 72];   // [m][k], stride 72 (pad 8)
    __shared__ __half Ws[128 * 72];   // [n][k]

    const int tid  = threadIdx.x;
    const int wid  = tid >> 5;
    const int lane = tid & 31;
    const int g    = lane >> 2;       // 0..7
    const int c    = (lane & 3) * 2;  // 0,2,4,6
    const int mrow = (wid & 1) * 64;
    const int ncol = (wid >> 1) * 32;
    const int rowBase = blockIdx.x * 128;

    float acc[4][4][4];
#pragma unroll
    for (int mt = 0; mt < 4; mt++)
#pragma unroll
        for (int nt = 0; nt < 4; nt++)
#pragma unroll
            for (int q = 0; q < 4; q++) acc[mt][nt][q] = 0.f;

#pragma unroll
    for (int kc = 0; kc < DH; kc += 64) {
        __syncthreads();
        // stage A[128][64] and W[128][64] (8 halfs = uint4 per thread-chunk)
#pragma unroll
        for (int t = 0; t < 4; t++) {
            int idx = tid + t * 256;
            int row = idx >> 3;
            int ch  = (idx & 7) * 8;
            int grow = rowBase + row;
            if (grow >= M) grow = M - 1;
            *reinterpret_cast<uint4*>(&As[row * 72 + ch]) =
                *reinterpret_cast<const uint4*>(&g_agg16[grow * DH + kc + ch]);
            *reinterpret_cast<uint4*>(&Ws[row * 72 + ch]) =
                *reinterpret_cast<const uint4*>(&Wh[row * DH + kc + ch]);
        }
        __syncthreads();

#pragma unroll
        for (int kk = 0; kk < 4; kk++) {
            const int k0 = kk * 16;
            uint32_t af[4][4], bf[4][2];
#pragma unroll
            for (int mt = 0; mt < 4; mt++) {
                uint32_t aaddr = (uint32_t)__cvta_generic_to_shared(
                    &As[(mrow + mt * 16 + (lane & 15)) * 72 + k0 + ((lane >> 4) << 3)]);
                asm volatile(
                    "ldmatrix.sync.aligned.m8n8.x4.shared.b16 {%0,%1,%2,%3}, [%4];"
                    : "=r"(af[mt][0]), "=r"(af[mt][1]),
                      "=r"(af[mt][2]), "=r"(af[mt][3])
                    : "r"(aaddr));
            }
#pragma unroll
            for (int nt = 0; nt < 4; nt++) {
                uint32_t baddr = (uint32_t)__cvta_generic_to_shared(
                    &Ws[(ncol + nt * 8 + (lane & 7)) * 72 + k0 + (((lane >> 3) & 1) << 3)]);
                asm volatile(
                    "ldmatrix.sync.aligned.m8n8.x2.shared.b16 {%0,%1}, [%2];"
                    : "=r"(bf[nt][0]), "=r"(bf[nt][1])
                    : "r"(baddr));
            }
#pragma unroll
            for (int mt = 0; mt < 4; mt++)
#pragma unroll
                for (int nt = 0; nt < 4; nt++) {
                    asm volatile(
                        "mma.sync.aligned.m16n8k16.row.col.f32.f16.f16.f32 "
                        "{%0,%1,%2,%3}, {%4,%5,%6,%7}, {%8,%9}, {%0,%1,%2,%3};"
                        : "+f"(acc[mt][nt][0]), "+f"(acc[mt][nt][1]),
                          "+f"(acc[mt][nt][2]), "+f"(acc[mt][nt][3])
                        : "r"(af[mt][0]), "r"(af[mt][1]), "r"(af[mt][2]), "r"(af[mt][3]),
                          "r"(bf[nt][0]), "r"(bf[nt][1]));
                }
        }
    }

    // epilogue
#pragma unroll
    for (int nt = 0; nt < 4; nt++) {
        int col = ncol + nt * 8 + c;
        float2 bb = *reinterpret_cast<const float2*>(&bias[col]);
#pragma unroll
        for (int mt = 0; mt < 4; mt++) {
            int row0 = rowBase + mrow + mt * 16 + g;
            int row1 = row0 + 8;
            float c0 = acc[mt][nt][0] + bb.x;
            float c1 = acc[mt][nt][1] + bb.y;
            float c2 = acc[mt][nt][2] + bb.x;
            float c3 = acc[mt][nt][3] + bb.y;
            if (RELU) {
                c0 = fmaxf(c0, 0.f); c1 = fmaxf(c1, 0.f);
                c2 = fmaxf(c2, 0.f); c3 = fmaxf(c3, 0.f);
            }
            if (POOL) {
                if (row0 < M) red2(&g_pool[batch[row0] * DH + col], c0, c1);
                if (row1 < M) red2(&g_pool[batch[row1] * DH + col], c2, c3);
            } else {
                if (row0 < M)
                    *reinterpret_cast<__half2*>(&g_h16[row0 * DH + col]) =
                        __floats2half2_rn(c0, c1);
                if (row1 < M)
                    *reinterpret_cast<__half2*>(&g_h16[row1 * DH + col]) =
                        __floats2half2_rn(c2, c3);
            }
        }
    }
}

// ---------------- head: out[g][o] = dot(pool[g]/cnt[g], Wg[o]) + bg[o] ------
__global__ void final_kernel(const float* __restrict__ Wg,
                             const float* __restrict__ bg,
                             float* __restrict__ out) {
    int g = blockIdx.x;
    int lane = threadIdx.x;
    float4 p = reinterpret_cast<const float4*>(g_pool)[g * 32 + lane];
    float c = fmaxf(g_cnt[g], 1.0f);
#pragma unroll
    for (int o = 0; o < 10; o++) {
        float4 w = reinterpret_cast<const float4*>(Wg)[o * 32 + lane];
        float s = p.x * w.x + p.y * w.y + p.z * w.z + p.w * w.w;
#pragma unroll
        for (int off = 16; off; off >>= 1) s += __shfl_xor_sync(0xffffffffu, s, off);
        if (lane == 0) out[g * 10 + o] = s / c + bg[o];
    }
}

// ---------------- launch ----------------------------------------------------
extern "C" void kernel_launch(void* const* d_in, const int* in_sizes, int n_in,
                              void* d_out, int out_size) {
    const float* x     = (const float*)d_in[0];
    const int*   ei    = (const int*)d_in[1];      // int32 (JAX x64 disabled)
    const int*   batch = (const int*)d_in[2];
    const float* W0 = (const float*)d_in[3];
    const float* b0 = (const float*)d_in[4];
    const float* W1 = (const float*)d_in[5];
    const float* b1 = (const float*)d_in[6];
    const float* W2 = (const float*)d_in[7];
    const float* b2 = (const float*)d_in[8];
    const float* Wg = (const float*)d_in[9];
    const float* bg = (const float*)d_in[10];
    float* out = (float*)d_out;

    const int N = in_sizes[0] / DH;     // 100000
    const int E = in_sizes[1] / 2;      // 1600000

    const int gemm_grid = (N + 127) / 128;
    const int gat_grid  = (N + 15) / 16;  // 16 nodes/block (16 lanes/node, 256 thr)
    const int n4 = N * (DH / 4);

    __half* w16;
    cudaGetSymbolAddress((void**)&w16, g_w16);

    // CSR build + init + fp16 conversions
    init_kernel<<<(NGRAPH * DH > N ? NGRAPH * DH : N) / 512 + 1, 512>>>(N);
    hist_count_kernel<<<(E + 511) / 512, 512>>>(ei, batch, E, N);
    scan_kernel<<<1, 1024>>>(N);
    fill_kernel<<<(E + 511) / 512, 512>>>(ei, E);
    convert_x_kernel<<<(n4 + 511) / 512, 512>>>(reinterpret_cast<const float4*>(x), n4);
    convert_w_kernel<<<8, 512>>>(reinterpret_cast<const float4*>(W0), 0);
    convert_w_kernel<<<8, 512>>>(reinterpret_cast<const float4*>(W1), 1);
    convert_w_kernel<<<8, 512>>>(reinterpret_cast<const float4*>(W2), 2);

    __half* x16;  cudaGetSymbolAddress((void**)&x16, g_x16);
    __half* h16;  cudaGetSymbolAddress((void**)&h16, g_h16);

    // layer 0
    gather16_kernel<<<gat_grid, 256>>>(x16, N);
    hgemm_kernel<true, false><<<gemm_grid, 256>>>(w16, b0, nullptr, N);
    // layer 1
    gather16_kernel<<<gat_grid, 256>>>(h16, N);
    hgemm_kernel<true, false><<<gemm_grid, 256>>>(w16 + DH * DH, b1, nullptr, N);
    // layer 2 + fused pooling
    gather16_kernel<<<gat_grid, 256>>>(h16, N);
    hgemm_kernel<false, true><<<gemm_grid, 256>>>(w16 + 2 * DH * DH, b2, batch, N);

    final_kernel<<<NGRAPH, 32>>>(Wg, bg, out);
}